// round 8
// baseline (speedup 1.0000x reference)
#include <cuda_runtime.h>

// out = outer(w, x) @ x0 + bias + x  ==  w * dot(x, x0) + bias + x
// D = 8192 floats = 2048 float4.
// 8 CTAs x 256 threads, single launch, one barrier (R6 structure, best=6.56us).
// R8: packed f32x2 math (FFMA2/FADD2) halves FMA instruction count in the dot
// phase and epilogue — sm_103a packed pipe, PTX-only.

#define NCTAS 8
#define NTHR  256
#define NWARP (NTHR / 32)
#define V4_TOTAL 2048
#define V4_PER_T (V4_TOTAL / NTHR)    // 8
#define V4_PER_CTA (V4_TOTAL / NCTAS) // 256

typedef unsigned long long u64;

__device__ __forceinline__ u64 pack2(float lo, float hi) {
    u64 r; asm("mov.b64 %0, {%1, %2};" : "=l"(r) : "f"(lo), "f"(hi)); return r;
}
__device__ __forceinline__ void unpack2(u64 v, float& lo, float& hi) {
    asm("mov.b64 {%0, %1}, %2;" : "=f"(lo), "=f"(hi) : "l"(v));
}
__device__ __forceinline__ u64 fma2(u64 a, u64 b, u64 c) {
    u64 r; asm("fma.rn.f32x2 %0, %1, %2, %3;" : "=l"(r) : "l"(a), "l"(b), "l"(c)); return r;
}
__device__ __forceinline__ u64 add2(u64 a, u64 b) {
    u64 r; asm("add.rn.f32x2 %0, %1, %2;" : "=l"(r) : "l"(a), "l"(b)); return r;
}
__device__ __forceinline__ u64 mul2(u64 a, u64 b) {
    u64 r; asm("mul.rn.f32x2 %0, %1, %2;" : "=l"(r) : "l"(a), "l"(b)); return r;
}

__global__ void __launch_bounds__(NTHR) cross_fused_kernel(const float4* __restrict__ x0,
                                                           const float4* __restrict__ x,
                                                           const float4* __restrict__ w,
                                                           const float4* __restrict__ b,
                                                           float4* __restrict__ out) {
    const int t = threadIdx.x;

    // ---- Front-batch ALL loads (19 independent LDG.128) ----
    float4 a[V4_PER_T], xv[V4_PER_T];
    #pragma unroll
    for (int k = 0; k < V4_PER_T; k++) {
        a[k]  = x0[t + k * NTHR];
        xv[k] = x[t + k * NTHR];
    }
    const int ei = blockIdx.x * V4_PER_CTA + t;
    float4 wv = w[ei];
    float4 bv = b[ei];
    float4 xe = x[ei];

    // Epilogue additive part (independent of reduction), packed: 2 FADD2.
    u64 cv_lo = add2(pack2(bv.x, bv.y), pack2(xe.x, xe.y));
    u64 cv_hi = add2(pack2(bv.z, bv.w), pack2(xe.z, xe.w));

    // ---- Partial dot: 16 FFMA2 in 4 independent chains (depth 4) ----
    u64 acc0 = mul2(pack2(a[0].x, a[0].y), pack2(xv[0].x, xv[0].y));
    u64 acc1 = mul2(pack2(a[0].z, a[0].w), pack2(xv[0].z, xv[0].w));
    u64 acc2 = mul2(pack2(a[1].x, a[1].y), pack2(xv[1].x, xv[1].y));
    u64 acc3 = mul2(pack2(a[1].z, a[1].w), pack2(xv[1].z, xv[1].w));
    #pragma unroll
    for (int k = 2; k < V4_PER_T; k += 2) {
        acc0 = fma2(pack2(a[k].x,   a[k].y),   pack2(xv[k].x,   xv[k].y),   acc0);
        acc1 = fma2(pack2(a[k].z,   a[k].w),   pack2(xv[k].z,   xv[k].w),   acc1);
        acc2 = fma2(pack2(a[k+1].x, a[k+1].y), pack2(xv[k+1].x, xv[k+1].y), acc2);
        acc3 = fma2(pack2(a[k+1].z, a[k+1].w), pack2(xv[k+1].z, xv[k+1].w), acc3);
    }
    u64 accp = add2(add2(acc0, acc1), add2(acc2, acc3));
    float slo, shi;
    unpack2(accp, slo, shi);
    float s = slo + shi;

    // ---- Warp reduction: 5-shfl tree ----
    #pragma unroll
    for (int o = 16; o > 0; o >>= 1)
        s += __shfl_xor_sync(0xFFFFFFFFu, s, o);

    __shared__ float4 ws4[NWARP / 4];   // 8 warp sums as 2 float4
    float* ws = (float*)ws4;
    const int warp = t >> 5;
    const int lane = t & 31;
    if (lane == 0) ws[warp] = s;
    __syncthreads();

    // Broadcast-load 8 warp sums (2x LDS.128); packed combine: 3 FADD2 + 1 FADD.
    float4 u0 = ws4[0];
    float4 u1 = ws4[1];
    u64 v0 = add2(pack2(u0.x, u0.y), pack2(u0.z, u0.w));
    u64 v1 = add2(pack2(u1.x, u1.y), pack2(u1.z, u1.w));
    u64 vt = add2(v0, v1);
    float tlo, thi;
    unpack2(vt, tlo, thi);
    const float sv = tlo + thi;

    // ---- Epilogue: out = w*s + (b + x), packed: 2 FFMA2 ----
    u64 sv2 = pack2(sv, sv);
    u64 o_lo = fma2(pack2(wv.x, wv.y), sv2, cv_lo);
    u64 o_hi = fma2(pack2(wv.z, wv.w), sv2, cv_hi);
    float4 o;
    unpack2(o_lo, o.x, o.y);
    unpack2(o_hi, o.z, o.w);
    out[ei] = o;
}

extern "C" void kernel_launch(void* const* d_in, const int* in_sizes, int n_in,
                              void* d_out, int out_size) {
    const float4* x0 = (const float4*)d_in[0];
    const float4* x  = (const float4*)d_in[1];
    const float4* w  = (const float4*)d_in[2];
    const float4* b  = (const float4*)d_in[3];
    float4* out = (float4*)d_out;

    cross_fused_kernel<<<NCTAS, NTHR>>>(x0, x, w, b, out);
}